// round 12
// baseline (speedup 1.0000x reference)
#include <cuda_runtime.h>
#include <math.h>
#include <stdint.h>

// Problem constants
#define B_   8
#define N_   512
#define D_   256
#define R_   6
#define BN_  (B_*N_)          // 4096 rows
#define KA_  1568             // 6*256 rel cols + 6 count cols + pad

// Output layout in d_out (floats)
#define OFF_INTERP 1048576
#define OFF_SYM    (1048576 + 3*4096)

// ---------------- scratch ----------------
__device__ float    g_S0[BN_ * D_];
__device__ float    g_A[BN_ * KA_];
__device__ float    g_Wfull[KA_ * D_];
__device__ float    g_Wcat[D_ * 4 * D_];    // [k][1024]: 3 head W's + outW
__device__ float    g_bcat[4 * D_];
__device__ float    g_H[BN_ * 3 * D_];
__device__ float    g_P[B_ * (N_ + 1) * D_];
__device__ int      g_sidx[B_ * N_];
__device__ int      g_k0o[B_ * N_];         // band bounds per ORIGINAL index
__device__ int      g_k1o[B_ * N_];
__device__ uint32_t g_code32[BN_ * (N_/4)]; // relation code byte per (b,j,m), 4 packed

// ---------------- fused embed + code ----------------
__device__ __forceinline__ unsigned rel_code(float dx, float dy, bool self) {
    if (self)                    return 255u;
    if (dy > 0.5f)               return 0u;
    if (dy < -0.5f)              return 1u;
    if (dx < -0.5f)              return 2u;
    if (dx > 0.5f)               return 3u;
    if (fabsf(dx) < 0.3f && fabsf(dy) < 0.3f) return 4u;
    return 5u;
}

// grid 4096+128: blocks [0,4096) embed rows; blocks [4096,4224) code tiles
__global__ void k_pre(const int* __restrict__ ids,
                      const float* __restrict__ symt,
                      const float* __restrict__ layt,
                      const float* __restrict__ pos) {
    __shared__ float xm[N_], ym[N_];
    int t = threadIdx.x;
    if (blockIdx.x < 4096) {
        int row = blockIdx.x;
        int id  = ids[row];
        g_S0[row * D_ + t] = symt[id * D_ + t] + layt[id * D_ + t];
        return;
    }
    int blk = blockIdx.x - 4096;        // 0..127
    int b   = blk >> 4;
    int j0  = (blk & 15) * 32;
    for (int i = t; i < N_; i += 256) {
        xm[i] = pos[(b * N_ + i) * 2 + 0];
        ym[i] = pos[(b * N_ + i) * 2 + 1];
    }
    __syncthreads();
    for (int idx = t; idx < 32 * 128; idx += 256) {
        int jl = idx >> 7;
        int mg = idx & 127;
        int j  = j0 + jl;
        float xj = xm[j], yj = ym[j];
        uint32_t w = 0;
#pragma unroll
        for (int u = 0; u < 4; u++) {
            int m = mg * 4 + u;
            unsigned c = rel_code(xj - xm[m], yj - ym[m], m == j);
            w |= c << (u * 8);
        }
        g_code32[(size_t)(b * N_ + j) * 128 + mg] = w;
    }
}

__global__ void k_sort(const float* __restrict__ pos) {
    __shared__ float key[N_];
    __shared__ int   val[N_];
    int b = blockIdx.x, t = threadIdx.x;
    key[t] = pos[(b * N_ + t) * 2 + 1];
    val[t] = t;
    __syncthreads();
    for (int size = 2; size <= N_; size <<= 1) {
        for (int stride = size >> 1; stride > 0; stride >>= 1) {
            int j = t ^ stride;
            if (j > t) {
                bool up = ((t & size) == 0);
                float kt = key[t], kj = key[j];
                if ((kt > kj) == up) {
                    key[t] = kj; key[j] = kt;
                    int vt = val[t]; val[t] = val[j]; val[j] = vt;
                }
            }
            __syncthreads();
        }
    }
    g_sidx[b * N_ + t] = val[t];
    float y  = key[t];
    float v0 = y - 0.5f, v1 = y + 0.5f;
    int lo = 0, hi = N_;
    while (lo < hi) { int m = (lo + hi) >> 1; if (key[m] <  v0) lo = m + 1; else hi = m; }
    int k0 = lo;
    lo = 0; hi = N_;
    while (lo < hi) { int m = (lo + hi) >> 1; if (key[m] <= v1) lo = m + 1; else hi = m; }
    int orig = val[t];
    g_k0o[b * N_ + orig] = k0;
    g_k1o[b * N_ + orig] = lo;
}

// parallel prefix: grid = B*8 (32-ch groups), block = 1024 (32 warps x 16 serial rows)
__global__ void __launch_bounds__(1024) k_prefix() {
    __shared__ float ssum[32][33];
    int b    = blockIdx.x >> 3;
    int g    = blockIdx.x & 7;
    int lane = threadIdx.x & 31;
    int w    = threadIdx.x >> 5;     // segment 0..31
    int ch   = g * 32 + lane;
    const int* si = &g_sidx[b * N_];
    int m0 = w * 16;
    float s = 0.f;
#pragma unroll
    for (int m = 0; m < 16; m++)
        s += g_S0[(b * N_ + si[m0 + m]) * D_ + ch];
    ssum[w][lane] = s;
    __syncthreads();
    float run = 0.f;
    for (int q = 0; q < w; q++) run += ssum[q][lane];
    float* Pb = &g_P[(size_t)(b * (N_ + 1)) * D_ + ch];
#pragma unroll
    for (int m = 0; m < 16; m++) {
        Pb[(size_t)(m0 + m) * D_] = run;
        run += g_S0[(b * N_ + si[m0 + m]) * D_ + ch];
    }
    if (w == 31) Pb[(size_t)N_ * D_] = run;
}

// merged weight-prep: Wfull (grammar) + Wcat/bcat (heads+out)
__global__ void k_weights(const float* __restrict__ relW, const float* __restrict__ relb,
                          const float* __restrict__ h1W, const float* __restrict__ h1b,
                          const float* __restrict__ outW, const float* __restrict__ outb) {
    const int W1 = KA_ * D_;
    const int W2 = W1 + 1024 * D_;
    int idx = blockIdx.x * 256 + threadIdx.x;
    if (idx < W1) {
        int row = idx / D_, e = idx % D_;
        float v;
        if (row < R_ * D_)            v = relW[idx];
        else if (row < R_ * D_ + R_)  v = relb[(row - R_ * D_) * D_ + e];
        else                          v = 0.f;
        g_Wfull[idx] = v;
    } else if (idx < W2) {
        int i = idx - W1;
        int k = i >> 10, n = i & 1023;
        g_Wcat[i] = (n < 768) ? h1W[((n >> 8) * D_ + k) * D_ + (n & 255)]
                              : outW[k * D_ + (n - 768)];
    } else if (idx < W2 + 1024) {
        int i = idx - W2;
        g_bcat[i] = (i < 768) ? h1b[(i >> 8) * D_ + (i & 255)] : outb[i - 768];
    }
}

// ---------------- tf32 helpers ----------------
__device__ __forceinline__ uint32_t f2tf32(float x) {
    uint32_t r;
    asm("cvt.rna.tf32.f32 %0, %1;" : "=r"(r) : "f"(x));
    return r;
}

__device__ __forceinline__ void mma_tf32(float* c, uint32_t a0, uint32_t a1,
                                         uint32_t a2, uint32_t a3,
                                         uint32_t b0, uint32_t b1) {
    asm volatile(
        "mma.sync.aligned.m16n8k8.row.col.f32.tf32.tf32.f32 "
        "{%0,%1,%2,%3}, {%4,%5,%6,%7}, {%8,%9}, {%0,%1,%2,%3};"
        : "+f"(c[0]), "+f"(c[1]), "+f"(c[2]), "+f"(c[3])
        : "r"(a0), "r"(a1), "r"(a2), "r"(a3), "r"(b0), "r"(b1));
}

// ---------------- masked band GEMM + full A-row epilogue ----------------
// grid (4 ch-tiles, 8 j-tiles, 8 b), 256 thr (8 warps: 4 j-slabs x 2 ch-slabs)
// BM=64 (j), BN=64 (ch), K=512 (m). Single tf32 pass (masks exact; S_hi only).
__global__ void __launch_bounds__(256, 3) k_mgband() {
    __shared__ uint32_t      BsH[64 * 36];
    __shared__ unsigned char Cs[64 * 40];
    __shared__ int           cnt[64][4];
    __shared__ int           sk0[64], sk1[64];

    int b   = blockIdx.z;
    int j0  = blockIdx.y * 64;
    int ch0 = blockIdx.x * 64;
    int t    = threadIdx.x;
    int warp = t >> 5, lane = t & 31;
    int wm = warp >> 1;
    int wn = warp & 1;
    int qr = lane >> 2, qc = lane & 3;
    bool count_blk = (blockIdx.x == 0);

    if (t < 64) {
        sk0[t] = g_k0o[b * N_ + j0 + t];
        sk1[t] = g_k1o[b * N_ + j0 + t];
        cnt[t][0] = 0; cnt[t][1] = 0; cnt[t][2] = 0;
    }
    __syncthreads();

    float acc[3][4][4];
#pragma unroll
    for (int r = 0; r < 3; r++)
#pragma unroll
        for (int nt = 0; nt < 4; nt++)
#pragma unroll
            for (int f = 0; f < 4; f++) acc[r][nt][f] = 0.f;

    const uint32_t ONE = 0x3F800000u;

    for (int kt = 0; kt < N_; kt += 32) {
#pragma unroll
        for (int l = 0; l < 2; l++) {
            int w  = t + l * 256;
            int j  = w >> 3, kw = w & 7;
            uint32_t cw = g_code32[(size_t)(b * N_ + j0 + j) * 128 + (kt >> 2) + kw];
            *(uint32_t*)&Cs[j * 40 + kw * 4] = cw;
            if (count_blk) {
                int n2 = __popc(__vcmpeq4(cw, 0x02020202u)) >> 3;
                int n3 = __popc(__vcmpeq4(cw, 0x03030303u)) >> 3;
                int n4 = __popc(__vcmpeq4(cw, 0x04040404u)) >> 3;
                if (n2) atomicAdd(&cnt[j][0], n2);
                if (n3) atomicAdd(&cnt[j][1], n3);
                if (n4) atomicAdd(&cnt[j][2], n4);
            }
        }
#pragma unroll
        for (int l = 0; l < 8; l++) {
            int id = t + l * 256;
            int k  = id >> 6, n = id & 63;
            float v = g_S0[(size_t)(b * N_ + kt + k) * D_ + ch0 + n];
            BsH[n * 36 + k] = f2tf32(v);
        }
        __syncthreads();

#pragma unroll
        for (int ks = 0; ks < 32; ks += 8) {
            int k0 = ks + qc;
            int rb = wm * 16 + qr;
            unsigned c00 = Cs[rb * 40 + k0];
            unsigned c10 = Cs[(rb + 8) * 40 + k0];
            unsigned c01 = Cs[rb * 40 + k0 + 4];
            unsigned c11 = Cs[(rb + 8) * 40 + k0 + 4];
            uint32_t bh[8];
#pragma unroll
            for (int nt = 0; nt < 4; nt++) {
                int nb = wn * 32 + nt * 8 + qr;
                bh[nt*2+0] = BsH[nb * 36 + k0];
                bh[nt*2+1] = BsH[nb * 36 + k0 + 4];
            }
#pragma unroll
            for (int r = 0; r < 3; r++) {
                unsigned cr = r + 2;
                uint32_t a0 = (c00 == cr) ? ONE : 0u;
                uint32_t a1 = (c10 == cr) ? ONE : 0u;
                uint32_t a2 = (c01 == cr) ? ONE : 0u;
                uint32_t a3 = (c11 == cr) ? ONE : 0u;
#pragma unroll
                for (int nt = 0; nt < 4; nt++)
                    mma_tf32(acc[r][nt], a0, a1, a2, a3, bh[nt*2], bh[nt*2+1]);
            }
        }
        __syncthreads();
    }

    const float* Pb = &g_P[(size_t)(b * (N_ + 1)) * D_];
#pragma unroll
    for (int f = 0; f < 4; f++) {
        int rl   = wm * 16 + qr + ((f >= 2) ? 8 : 0);
        int grow = b * N_ + j0 + rl;
        int k0r = sk0[rl], k1r = sk1[rl];
        float* Ar = &g_A[(size_t)grow * KA_];
#pragma unroll
        for (int nt = 0; nt < 4; nt++) {
            int col = ch0 + wn * 32 + nt * 8 + qc * 2 + (f & 1);
            float p0  = Pb[(size_t)k0r * D_ + col];
            float p1  = Pb[(size_t)k1r * D_ + col];
            float tot = Pb[(size_t)N_ * D_ + col];
            float sj  = g_S0[(size_t)grow * D_ + col];
            float a2v = acc[0][nt][f];
            float a3v = acc[1][nt][f];
            float a4v = acc[2][nt][f];
            Ar[0 * D_ + col] = p0;
            Ar[1 * D_ + col] = tot - p1;
            Ar[2 * D_ + col] = a2v;
            Ar[3 * D_ + col] = a3v;
            Ar[4 * D_ + col] = a4v;
            Ar[5 * D_ + col] = (p1 - p0 - sj) - a2v - a3v - a4v;
        }
    }
    if (count_blk) {
        __syncthreads();
        if (t < 64) {
            int k0r = sk0[t], k1r = sk1[t];
            int n2 = cnt[t][0], n3 = cnt[t][1], n4 = cnt[t][2];
            float* Ar = &g_A[(size_t)(b * N_ + j0 + t) * KA_ + R_ * D_];
#pragma unroll
            for (int c = 0; c < 32; c++) {
                float cv = 0.f;
                if (c == 0)      cv = (float)k0r;
                else if (c == 1) cv = (float)(N_ - k1r);
                else if (c == 2) cv = (float)n2;
                else if (c == 3) cv = (float)n3;
                else if (c == 4) cv = (float)n4;
                else if (c == 5) cv = (float)((k1r - k0r - 1) - n2 - n3 - n4);
                Ar[c] = cv;
            }
        }
    }
}

// ---------------- main GEMMs: tf32 3-pass, fragment-packed smem ----------------
// Packed layout: one float4 per (row, ks-group g, qc) = {hi(k0), hi(k0+4), lo(k0), lo(k0+4)}
// where k0 = g*8+qc. Row stride 17 float4 (bank-permute). Mainloop = LDS.128 only.
// BM=128, BN=64, 256 thr (8 warps: 4m x 2n), K%32==0.
#define ASTRIDE 17
#define SMEM_F4 ((128 + 64) * ASTRIDE)
#define SMEM_BYTES (SMEM_F4 * 16)

// MODE 0: C = A@Bm + addp  (grammar)
// MODE 1: fused heads+out  (cols<768: gelu -> C(ld 768); else -> C2(ld 256))
template<int MODE>
__global__ void __launch_bounds__(256) mgemm2(
        const float* __restrict__ A, int lda,
        const float* __restrict__ Bm, int ldb, int K,
        const float* __restrict__ addp,
        float* __restrict__ C, float* __restrict__ C2) {
    extern __shared__ float4 smf4[];
    float4* AsP = smf4;                   // [128][ASTRIDE]
    float4* BsP = smf4 + 128 * ASTRIDE;   // [64][ASTRIDE]

    int t    = threadIdx.x;
    int warp = t >> 5, lane = t & 31;
    int wm   = warp >> 1;
    int wn   = warp & 1;
    int bm0  = blockIdx.y * 128;
    int bn0  = blockIdx.x * 64;
    int qr   = lane >> 2;
    int qc   = lane & 3;

    float acc[2][4][4];
#pragma unroll
    for (int mt = 0; mt < 2; mt++)
#pragma unroll
        for (int nt = 0; nt < 4; nt++)
#pragma unroll
            for (int f = 0; f < 4; f++) acc[mt][nt][f] = 0.f;

    for (int kt = 0; kt < K; kt += 32) {
        // stage A [128 x 32] -> packed hi/lo
#pragma unroll
        for (int l = 0; l < 4; l++) {
            int id   = t + l * 256;
            int row  = id >> 3;
            int kq   = (id & 7) * 4;         // 0,4,..,28
            int g    = kq >> 3;
            int half = (kq >> 2) & 1;
            float4 v = *(const float4*)&A[(size_t)(bm0 + row) * lda + kt + kq];
            float* base = (float*)&AsP[row * ASTRIDE + g * 4];
            float fe[4] = {v.x, v.y, v.z, v.w};
#pragma unroll
            for (int j = 0; j < 4; j++) {
                uint32_t h = f2tf32(fe[j]);
                base[j * 4 + half]     = __uint_as_float(h);
                base[j * 4 + 2 + half] = __uint_as_float(f2tf32(fe[j] - __uint_as_float(h)));
            }
        }
        // stage B [32 x 64] -> packed hi/lo, [n][g][qc]
#pragma unroll
        for (int l = 0; l < 8; l++) {
            int id   = t + l * 256;
            int k    = id >> 6;              // 0..31
            int n    = id & 63;
            int g    = k >> 3;
            int qck  = k & 3;
            int half = (k >> 2) & 1;
            float v = Bm[(size_t)(kt + k) * ldb + bn0 + n];
            uint32_t h = f2tf32(v);
            float* base = (float*)&BsP[n * ASTRIDE + g * 4 + qck];
            base[half]     = __uint_as_float(h);
            base[2 + half] = __uint_as_float(f2tf32(v - __uint_as_float(h)));
        }
        __syncthreads();

#pragma unroll
        for (int g = 0; g < 4; g++) {
            // A fragments: 2 m-tiles, rows rb & rb+8
            uint32_t ahi[8], alo[8];
#pragma unroll
            for (int mt = 0; mt < 2; mt++) {
                int rb = wm * 32 + mt * 16 + qr;
                float4 va = AsP[rb * ASTRIDE + g * 4 + qc];
                float4 vb = AsP[(rb + 8) * ASTRIDE + g * 4 + qc];
                ahi[mt*4+0] = __float_as_uint(va.x);
                ahi[mt*4+1] = __float_as_uint(vb.x);
                ahi[mt*4+2] = __float_as_uint(va.y);
                ahi[mt*4+3] = __float_as_uint(vb.y);
                alo[mt*4+0] = __float_as_uint(va.z);
                alo[mt*4+1] = __float_as_uint(vb.z);
                alo[mt*4+2] = __float_as_uint(va.w);
                alo[mt*4+3] = __float_as_uint(vb.w);
            }
            uint32_t bhi[8], blo[8];
#pragma unroll
            for (int nt = 0; nt < 4; nt++) {
                int nb = wn * 32 + nt * 8 + qr;
                float4 vb = BsP[nb * ASTRIDE + g * 4 + qc];
                bhi[nt*2+0] = __float_as_uint(vb.x);
                bhi[nt*2+1] = __float_as_uint(vb.y);
                blo[nt*2+0] = __float_as_uint(vb.z);
                blo[nt*2+1] = __float_as_uint(vb.w);
            }
#pragma unroll
            for (int mt = 0; mt < 2; mt++)
#pragma unroll
                for (int nt = 0; nt < 4; nt++) {
                    float* c = acc[mt][nt];
                    mma_tf32(c, ahi[mt*4], ahi[mt*4+1], ahi[mt*4+2], ahi[mt*4+3],
                             bhi[nt*2], bhi[nt*2+1]);
                    mma_tf32(c, alo[mt*4], alo[mt*4+1], alo[mt*4+2], alo[mt*4+3],
                             bhi[nt*2], bhi[nt*2+1]);
                    mma_tf32(c, ahi[mt*4], ahi[mt*4+1], ahi[mt*4+2], ahi[mt*4+3],
                             blo[nt*2], blo[nt*2+1]);
                }
        }
        __syncthreads();
    }

#pragma unroll
    for (int mt = 0; mt < 2; mt++) {
#pragma unroll
        for (int f = 0; f < 4; f++) {
            int row = bm0 + wm * 32 + mt * 16 + qr + ((f >= 2) ? 8 : 0);
#pragma unroll
            for (int nt = 0; nt < 4; nt++) {
                int col = bn0 + wn * 32 + nt * 8 + qc * 2 + (f & 1);
                float v = acc[mt][nt][f];
                if (MODE == 0) {
                    v += addp[(size_t)row * D_ + col];
                    C[(size_t)row * D_ + col] = v;
                } else {
                    v += g_bcat[col];
                    if (bn0 < 768) {
                        v = 0.5f * v * (1.f + erff(v * 0.70710678118654752440f));
                        C[(size_t)row * 768 + col] = v;
                    } else {
                        C2[(size_t)row * D_ + (col - 768)] = v;
                    }
                }
            }
        }
    }
}

__global__ void k_interp(const float* __restrict__ h2W, const float* __restrict__ h2b,
                         float* __restrict__ out) {
    int row  = blockIdx.x;
    int wid  = threadIdx.x >> 5;
    int lane = threadIdx.x & 31;
    const float* hrow = &g_H[(size_t)row * (3 * D_) + wid * D_];
    const float* w    = &h2W[wid * D_];
    float s = 0.f;
    for (int e = lane; e < D_; e += 32) s += hrow[e] * w[e];
#pragma unroll
    for (int o = 16; o; o >>= 1) s += __shfl_xor_sync(0xffffffffu, s, o);
    if (lane == 0) out[OFF_INTERP + wid * BN_ + row] = s + h2b[wid];
}

// ---------------- launch ----------------
extern "C" void kernel_launch(void* const* d_in, const int* in_sizes, int n_in,
                              void* d_out, int out_size) {
    const int*   ids  = (const int*)  d_in[0];
    const float* pos  = (const float*)d_in[1];
    const float* symt = (const float*)d_in[2];
    const float* layt = (const float*)d_in[3];
    const float* relW = (const float*)d_in[4];
    const float* relb = (const float*)d_in[5];
    const float* h1W  = (const float*)d_in[6];
    const float* h1b  = (const float*)d_in[7];
    const float* h2W  = (const float*)d_in[8];
    const float* h2b  = (const float*)d_in[9];
    const float* outW = (const float*)d_in[10];
    const float* outb = (const float*)d_in[11];
    float* out = (float*)d_out;

    float *pA, *pW, *pWc, *pH, *pS0;
    cudaGetSymbolAddress((void**)&pA,  g_A);
    cudaGetSymbolAddress((void**)&pW,  g_Wfull);
    cudaGetSymbolAddress((void**)&pWc, g_Wcat);
    cudaGetSymbolAddress((void**)&pH,  g_H);
    cudaGetSymbolAddress((void**)&pS0, g_S0);

    cudaFuncSetAttribute((const void*)mgemm2<0>,
                         cudaFuncAttributeMaxDynamicSharedMemorySize, SMEM_BYTES);
    cudaFuncSetAttribute((const void*)mgemm2<1>,
                         cudaFuncAttributeMaxDynamicSharedMemorySize, SMEM_BYTES);

    // order: slot #3 (0-indexed) = k_mgband -> profiled by ncu
    k_pre   <<<4096 + 128, 256>>>(ids, symt, layt, pos);
    k_sort  <<<B_, N_>>>(pos);
    k_prefix<<<B_ * 8, 1024>>>();
    k_mgband<<<dim3(4, 8, 8), 256>>>();
    {
        int total = KA_ * D_ + 1024 * D_ + 1024;
        k_weights<<<(total + 255) / 256, 256>>>(relW, relb, h1W, h1b, outW, outb);
    }

    float* d_sym = out + OFF_SYM;
    // grammar: symbols = S0 + A @ Wfull  (BM128 x BN64, grid 4x32 = 128 blocks)
    mgemm2<0><<<dim3(D_ / 64, BN_ / 128), 256, SMEM_BYTES>>>(
        pA, KA_, pW, D_, KA_, pS0, d_sym, nullptr);
    // fused heads (gelu -> g_H) + output projection (-> out)
    mgemm2<1><<<dim3(1024 / 64, BN_ / 128), 256, SMEM_BYTES>>>(
        d_sym, D_, pWc, 1024, D_, nullptr, pH, out);

    k_interp<<<BN_, 96>>>(h2W, h2b, out);
}

// round 13
// speedup vs baseline: 1.0634x; 1.0634x over previous
#include <cuda_runtime.h>
#include <math.h>
#include <stdint.h>

// Problem constants
#define B_   8
#define N_   512
#define D_   256
#define R_   6
#define BN_  (B_*N_)          // 4096 rows
#define KA_  1568             // 6*256 rel cols + 6 count cols + pad

// Output layout in d_out (floats)
#define OFF_INTERP 1048576
#define OFF_SYM    (1048576 + 3*4096)

// ---------------- scratch ----------------
__device__ float    g_S0[BN_ * D_];
__device__ float    g_A[BN_ * KA_];
__device__ float    g_Wfull[KA_ * D_];
__device__ float    g_Wcat[D_ * 4 * D_];    // [k][1024]: 3 head W's + outW
__device__ float    g_bcat[4 * D_];
__device__ float    g_H[BN_ * 3 * D_];
__device__ float    g_P[B_ * (N_ + 1) * D_];
__device__ int      g_sidx[B_ * N_];
__device__ int      g_k0o[B_ * N_];         // band bounds per ORIGINAL index
__device__ int      g_k1o[B_ * N_];
__device__ uint32_t g_code32[BN_ * (N_/4)]; // relation code byte per (b,j,m), 4 packed

// ---------------- fused embed + code ----------------
__device__ __forceinline__ unsigned rel_code(float dx, float dy, bool self) {
    if (self)                    return 255u;
    if (dy > 0.5f)               return 0u;
    if (dy < -0.5f)              return 1u;
    if (dx < -0.5f)              return 2u;
    if (dx > 0.5f)               return 3u;
    if (fabsf(dx) < 0.3f && fabsf(dy) < 0.3f) return 4u;
    return 5u;
}

// grid 4096+128: blocks [0,4096) embed rows; blocks [4096,4224) code tiles
__global__ void k_pre(const int* __restrict__ ids,
                      const float* __restrict__ symt,
                      const float* __restrict__ layt,
                      const float* __restrict__ pos) {
    __shared__ float xm[N_], ym[N_];
    int t = threadIdx.x;
    if (blockIdx.x < 4096) {
        int row = blockIdx.x;
        int id  = ids[row];
        g_S0[row * D_ + t] = symt[id * D_ + t] + layt[id * D_ + t];
        return;
    }
    int blk = blockIdx.x - 4096;        // 0..127
    int b   = blk >> 4;
    int j0  = (blk & 15) * 32;
    for (int i = t; i < N_; i += 256) {
        xm[i] = pos[(b * N_ + i) * 2 + 0];
        ym[i] = pos[(b * N_ + i) * 2 + 1];
    }
    __syncthreads();
    for (int idx = t; idx < 32 * 128; idx += 256) {
        int jl = idx >> 7;
        int mg = idx & 127;
        int j  = j0 + jl;
        float xj = xm[j], yj = ym[j];
        uint32_t w = 0;
#pragma unroll
        for (int u = 0; u < 4; u++) {
            int m = mg * 4 + u;
            unsigned c = rel_code(xj - xm[m], yj - ym[m], m == j);
            w |= c << (u * 8);
        }
        g_code32[(size_t)(b * N_ + j) * 128 + mg] = w;
    }
}

__global__ void k_sort(const float* __restrict__ pos) {
    __shared__ float key[N_];
    __shared__ int   val[N_];
    int b = blockIdx.x, t = threadIdx.x;
    key[t] = pos[(b * N_ + t) * 2 + 1];
    val[t] = t;
    __syncthreads();
    for (int size = 2; size <= N_; size <<= 1) {
        for (int stride = size >> 1; stride > 0; stride >>= 1) {
            int j = t ^ stride;
            if (j > t) {
                bool up = ((t & size) == 0);
                float kt = key[t], kj = key[j];
                if ((kt > kj) == up) {
                    key[t] = kj; key[j] = kt;
                    int vt = val[t]; val[t] = val[j]; val[j] = vt;
                }
            }
            __syncthreads();
        }
    }
    g_sidx[b * N_ + t] = val[t];
    float y  = key[t];
    float v0 = y - 0.5f, v1 = y + 0.5f;
    int lo = 0, hi = N_;
    while (lo < hi) { int m = (lo + hi) >> 1; if (key[m] <  v0) lo = m + 1; else hi = m; }
    int k0 = lo;
    lo = 0; hi = N_;
    while (lo < hi) { int m = (lo + hi) >> 1; if (key[m] <= v1) lo = m + 1; else hi = m; }
    int orig = val[t];
    g_k0o[b * N_ + orig] = k0;
    g_k1o[b * N_ + orig] = lo;
}

// parallel prefix: grid = B*8 (32-ch groups), block = 1024 (32 warps x 16 serial rows)
__global__ void __launch_bounds__(1024) k_prefix() {
    __shared__ float ssum[32][33];
    int b    = blockIdx.x >> 3;
    int g    = blockIdx.x & 7;
    int lane = threadIdx.x & 31;
    int w    = threadIdx.x >> 5;     // segment 0..31
    int ch   = g * 32 + lane;
    const int* si = &g_sidx[b * N_];
    int m0 = w * 16;
    float s = 0.f;
#pragma unroll
    for (int m = 0; m < 16; m++)
        s += g_S0[(b * N_ + si[m0 + m]) * D_ + ch];
    ssum[w][lane] = s;
    __syncthreads();
    float run = 0.f;
    for (int q = 0; q < w; q++) run += ssum[q][lane];
    float* Pb = &g_P[(size_t)(b * (N_ + 1)) * D_ + ch];
#pragma unroll
    for (int m = 0; m < 16; m++) {
        Pb[(size_t)(m0 + m) * D_] = run;
        run += g_S0[(b * N_ + si[m0 + m]) * D_ + ch];
    }
    if (w == 31) Pb[(size_t)N_ * D_] = run;
}

// merged weight-prep: Wfull (grammar) + Wcat/bcat (heads+out)
__global__ void k_weights(const float* __restrict__ relW, const float* __restrict__ relb,
                          const float* __restrict__ h1W, const float* __restrict__ h1b,
                          const float* __restrict__ outW, const float* __restrict__ outb) {
    const int W1 = KA_ * D_;
    const int W2 = W1 + 1024 * D_;
    int idx = blockIdx.x * 256 + threadIdx.x;
    if (idx < W1) {
        int row = idx / D_, e = idx % D_;
        float v;
        if (row < R_ * D_)            v = relW[idx];
        else if (row < R_ * D_ + R_)  v = relb[(row - R_ * D_) * D_ + e];
        else                          v = 0.f;
        g_Wfull[idx] = v;
    } else if (idx < W2) {
        int i = idx - W1;
        int k = i >> 10, n = i & 1023;
        g_Wcat[i] = (n < 768) ? h1W[((n >> 8) * D_ + k) * D_ + (n & 255)]
                              : outW[k * D_ + (n - 768)];
    } else if (idx < W2 + 1024) {
        int i = idx - W2;
        g_bcat[i] = (i < 768) ? h1b[(i >> 8) * D_ + (i & 255)] : outb[i - 768];
    }
}

// ---------------- tf32 helpers ----------------
__device__ __forceinline__ uint32_t f2tf32(float x) {
    uint32_t r;
    asm("cvt.rna.tf32.f32 %0, %1;" : "=r"(r) : "f"(x));
    return r;
}

__device__ __forceinline__ void mma_tf32(float* c, uint32_t a0, uint32_t a1,
                                         uint32_t a2, uint32_t a3,
                                         uint32_t b0, uint32_t b1) {
    asm volatile(
        "mma.sync.aligned.m16n8k8.row.col.f32.tf32.tf32.f32 "
        "{%0,%1,%2,%3}, {%4,%5,%6,%7}, {%8,%9}, {%0,%1,%2,%3};"
        : "+f"(c[0]), "+f"(c[1]), "+f"(c[2]), "+f"(c[3])
        : "r"(a0), "r"(a1), "r"(a2), "r"(a3), "r"(b0), "r"(b1));
}

// ---------------- masked band GEMM + full A-row epilogue ----------------
// grid (8 ch-tiles of 32, 8 j-tiles of 64, 8 b) = 512 blocks, 256 thr
// (8 warps: 4 j-slabs x 2 ch-slabs of 16). Single tf32 pass (masks exact).
__global__ void __launch_bounds__(256, 4) k_mgband() {
    __shared__ uint32_t      BsH[32 * 36];
    __shared__ unsigned char Cs[64 * 40];
    __shared__ int           cnt[64][4];
    __shared__ int           sk0[64], sk1[64];

    int b   = blockIdx.z;
    int j0  = blockIdx.y * 64;
    int ch0 = blockIdx.x * 32;
    int t    = threadIdx.x;
    int warp = t >> 5, lane = t & 31;
    int wm = warp >> 1;              // 0..3 -> 16-row j slab
    int wn = warp & 1;               // 0..1 -> 16-col ch slab
    int qr = lane >> 2, qc = lane & 3;
    bool count_blk = (blockIdx.x == 0);

    if (t < 64) {
        sk0[t] = g_k0o[b * N_ + j0 + t];
        sk1[t] = g_k1o[b * N_ + j0 + t];
        cnt[t][0] = 0; cnt[t][1] = 0; cnt[t][2] = 0;
    }
    __syncthreads();

    float acc[3][2][4];
#pragma unroll
    for (int r = 0; r < 3; r++)
#pragma unroll
        for (int nt = 0; nt < 2; nt++)
#pragma unroll
            for (int f = 0; f < 4; f++) acc[r][nt][f] = 0.f;

    const uint32_t ONE = 0x3F800000u;

    for (int kt = 0; kt < N_; kt += 32) {
        // stage codes [64 j x 32 m]; accumulate counts (ch-tile 0 only)
#pragma unroll
        for (int l = 0; l < 2; l++) {
            int w  = t + l * 256;
            int j  = w >> 3, kw = w & 7;
            uint32_t cw = g_code32[(size_t)(b * N_ + j0 + j) * 128 + (kt >> 2) + kw];
            *(uint32_t*)&Cs[j * 40 + kw * 4] = cw;
            if (count_blk) {
                int n2 = __popc(__vcmpeq4(cw, 0x02020202u)) >> 3;
                int n3 = __popc(__vcmpeq4(cw, 0x03030303u)) >> 3;
                int n4 = __popc(__vcmpeq4(cw, 0x04040404u)) >> 3;
                if (n2) atomicAdd(&cnt[j][0], n2);
                if (n3) atomicAdd(&cnt[j][1], n3);
                if (n4) atomicAdd(&cnt[j][2], n4);
            }
        }
        // stage S0 chunk [32 m x 32 ch] (hi only) as [n][k], stride 36
#pragma unroll
        for (int l = 0; l < 4; l++) {
            int id = t + l * 256;
            int k  = id >> 5, n = id & 31;
            float v = g_S0[(size_t)(b * N_ + kt + k) * D_ + ch0 + n];
            BsH[n * 36 + k] = f2tf32(v);
        }
        __syncthreads();

#pragma unroll
        for (int ks = 0; ks < 32; ks += 8) {
            int k0 = ks + qc;
            int rb = wm * 16 + qr;
            unsigned c00 = Cs[rb * 40 + k0];
            unsigned c10 = Cs[(rb + 8) * 40 + k0];
            unsigned c01 = Cs[rb * 40 + k0 + 4];
            unsigned c11 = Cs[(rb + 8) * 40 + k0 + 4];
            uint32_t bh[4];
#pragma unroll
            for (int nt = 0; nt < 2; nt++) {
                int nb = wn * 16 + nt * 8 + qr;
                bh[nt*2+0] = BsH[nb * 36 + k0];
                bh[nt*2+1] = BsH[nb * 36 + k0 + 4];
            }
#pragma unroll
            for (int r = 0; r < 3; r++) {
                unsigned cr = r + 2;
                uint32_t a0 = (c00 == cr) ? ONE : 0u;
                uint32_t a1 = (c10 == cr) ? ONE : 0u;
                uint32_t a2 = (c01 == cr) ? ONE : 0u;
                uint32_t a3 = (c11 == cr) ? ONE : 0u;
#pragma unroll
                for (int nt = 0; nt < 2; nt++)
                    mma_tf32(acc[r][nt], a0, a1, a2, a3, bh[nt*2], bh[nt*2+1]);
            }
        }
        __syncthreads();
    }

    // epilogue: full A row segments for this (j,ch) tile
    const float* Pb = &g_P[(size_t)(b * (N_ + 1)) * D_];
#pragma unroll
    for (int f = 0; f < 4; f++) {
        int rl   = wm * 16 + qr + ((f >= 2) ? 8 : 0);
        int grow = b * N_ + j0 + rl;
        int k0r = sk0[rl], k1r = sk1[rl];
        float* Ar = &g_A[(size_t)grow * KA_];
#pragma unroll
        for (int nt = 0; nt < 2; nt++) {
            int col = ch0 + wn * 16 + nt * 8 + qc * 2 + (f & 1);
            float p0  = Pb[(size_t)k0r * D_ + col];
            float p1  = Pb[(size_t)k1r * D_ + col];
            float tot = Pb[(size_t)N_ * D_ + col];
            float sj  = g_S0[(size_t)grow * D_ + col];
            float a2v = acc[0][nt][f];
            float a3v = acc[1][nt][f];
            float a4v = acc[2][nt][f];
            Ar[0 * D_ + col] = p0;
            Ar[1 * D_ + col] = tot - p1;
            Ar[2 * D_ + col] = a2v;
            Ar[3 * D_ + col] = a3v;
            Ar[4 * D_ + col] = a4v;
            Ar[5 * D_ + col] = (p1 - p0 - sj) - a2v - a3v - a4v;
        }
    }
    if (count_blk) {
        __syncthreads();
        if (t < 64) {
            int k0r = sk0[t], k1r = sk1[t];
            int n2 = cnt[t][0], n3 = cnt[t][1], n4 = cnt[t][2];
            float* Ar = &g_A[(size_t)(b * N_ + j0 + t) * KA_ + R_ * D_];
#pragma unroll
            for (int c = 0; c < 32; c++) {
                float cv = 0.f;
                if (c == 0)      cv = (float)k0r;
                else if (c == 1) cv = (float)(N_ - k1r);
                else if (c == 2) cv = (float)n2;
                else if (c == 3) cv = (float)n3;
                else if (c == 4) cv = (float)n4;
                else if (c == 5) cv = (float)((k1r - k0r - 1) - n2 - n3 - n4);
                Ar[c] = cv;
            }
        }
    }
}

// ---------------- main GEMMs (tf32 3-pass, hi/lo split smem) ----------------
// MODE 0: C = A@Bm + addp  (grammar)
// MODE 1: fused heads+out  (cols<768: gelu -> C(ld 768); else -> C2(ld 256))
// BM=128, BN=BNt, 256 thr (8 warps: 4m x 2n), K%32==0.
template<int MODE, int BNt>
__global__ void __launch_bounds__(256) mgemm2(
        const float* __restrict__ A, int lda,
        const float* __restrict__ Bm, int ldb, int K,
        const float* __restrict__ addp,
        float* __restrict__ C, float* __restrict__ C2) {
    constexpr int HALF = BNt / 2;
    constexpr int NT   = HALF / 8;
    extern __shared__ uint32_t sm[];
    uint32_t* AsH = sm;
    uint32_t* AsL = sm + 128 * 36;
    uint32_t* BsH = sm + 2 * 128 * 36;
    uint32_t* BsL = BsH + BNt * 36;

    int t    = threadIdx.x;
    int warp = t >> 5, lane = t & 31;
    int wm   = warp >> 1;
    int wn   = warp & 1;
    int bm0  = blockIdx.y * 128;
    int bn0  = blockIdx.x * BNt;
    int qr   = lane >> 2;
    int qc   = lane & 3;

    float acc[2][NT][4];
#pragma unroll
    for (int mt = 0; mt < 2; mt++)
#pragma unroll
        for (int nt = 0; nt < NT; nt++)
#pragma unroll
            for (int f = 0; f < 4; f++) acc[mt][nt][f] = 0.f;

    for (int kt = 0; kt < K; kt += 32) {
#pragma unroll
        for (int l = 0; l < 4; l++) {
            int id  = t + l * 256;
            int row = id >> 3;
            int kq  = (id & 7) * 4;
            float4 v = *(const float4*)&A[(size_t)(bm0 + row) * lda + kt + kq];
            float fe[4] = {v.x, v.y, v.z, v.w};
#pragma unroll
            for (int jj = 0; jj < 4; jj++) {
                uint32_t h = f2tf32(fe[jj]);
                AsH[row * 36 + kq + jj] = h;
                AsL[row * 36 + kq + jj] = f2tf32(fe[jj] - __uint_as_float(h));
            }
        }
#pragma unroll
        for (int l = 0; l < (BNt * 32) / 256; l++) {
            int id = t + l * 256;
            int k  = id / BNt;
            int n  = id % BNt;
            float v = Bm[(size_t)(kt + k) * ldb + bn0 + n];
            uint32_t h = f2tf32(v);
            BsH[n * 36 + k] = h;
            BsL[n * 36 + k] = f2tf32(v - __uint_as_float(h));
        }
        __syncthreads();

#pragma unroll
        for (int ks = 0; ks < 32; ks += 8) {
            int k0 = ks + qc;
            uint32_t ahi[8], alo[8];
#pragma unroll
            for (int mt = 0; mt < 2; mt++) {
                int rb = wm * 32 + mt * 16 + qr;
                ahi[mt*4+0] = AsH[rb * 36 + k0];
                ahi[mt*4+1] = AsH[(rb + 8) * 36 + k0];
                ahi[mt*4+2] = AsH[rb * 36 + k0 + 4];
                ahi[mt*4+3] = AsH[(rb + 8) * 36 + k0 + 4];
                alo[mt*4+0] = AsL[rb * 36 + k0];
                alo[mt*4+1] = AsL[(rb + 8) * 36 + k0];
                alo[mt*4+2] = AsL[rb * 36 + k0 + 4];
                alo[mt*4+3] = AsL[(rb + 8) * 36 + k0 + 4];
            }
            uint32_t bhi[2*NT], blo[2*NT];
#pragma unroll
            for (int nt = 0; nt < NT; nt++) {
                int nb = wn * HALF + nt * 8 + qr;
                bhi[nt*2+0] = BsH[nb * 36 + k0];
                bhi[nt*2+1] = BsH[nb * 36 + k0 + 4];
                blo[nt*2+0] = BsL[nb * 36 + k0];
                blo[nt*2+1] = BsL[nb * 36 + k0 + 4];
            }
#pragma unroll
            for (int mt = 0; mt < 2; mt++)
#pragma unroll
                for (int nt = 0; nt < NT; nt++) {
                    float* c = acc[mt][nt];
                    mma_tf32(c, ahi[mt*4], ahi[mt*4+1], ahi[mt*4+2], ahi[mt*4+3],
                             bhi[nt*2], bhi[nt*2+1]);
                    mma_tf32(c, alo[mt*4], alo[mt*4+1], alo[mt*4+2], alo[mt*4+3],
                             bhi[nt*2], bhi[nt*2+1]);
                    mma_tf32(c, ahi[mt*4], ahi[mt*4+1], ahi[mt*4+2], ahi[mt*4+3],
                             blo[nt*2], blo[nt*2+1]);
                }
        }
        __syncthreads();
    }

#pragma unroll
    for (int mt = 0; mt < 2; mt++) {
#pragma unroll
        for (int f = 0; f < 4; f++) {
            int row = bm0 + wm * 32 + mt * 16 + qr + ((f >= 2) ? 8 : 0);
#pragma unroll
            for (int nt = 0; nt < NT; nt++) {
                int col = bn0 + wn * HALF + nt * 8 + qc * 2 + (f & 1);
                float v = acc[mt][nt][f];
                if (MODE == 0) {
                    v += addp[(size_t)row * D_ + col];
                    C[(size_t)row * D_ + col] = v;
                } else {
                    v += g_bcat[col];
                    if (bn0 < 768) {
                        v = 0.5f * v * (1.f + erff(v * 0.70710678118654752440f));
                        C[(size_t)row * 768 + col] = v;
                    } else {
                        C2[(size_t)row * D_ + (col - 768)] = v;
                    }
                }
            }
        }
    }
}

__global__ void k_interp(const float* __restrict__ h2W, const float* __restrict__ h2b,
                         float* __restrict__ out) {
    int row  = blockIdx.x;
    int wid  = threadIdx.x >> 5;
    int lane = threadIdx.x & 31;
    const float* hrow = &g_H[(size_t)row * (3 * D_) + wid * D_];
    const float* w    = &h2W[wid * D_];
    float s = 0.f;
    for (int e = lane; e < D_; e += 32) s += hrow[e] * w[e];
#pragma unroll
    for (int o = 16; o; o >>= 1) s += __shfl_xor_sync(0xffffffffu, s, o);
    if (lane == 0) out[OFF_INTERP + wid * BN_ + row] = s + h2b[wid];
}

// ---------------- launch ----------------
#define SMB(BNt) ((2*128*36 + 2*(BNt)*36) * 4)

extern "C" void kernel_launch(void* const* d_in, const int* in_sizes, int n_in,
                              void* d_out, int out_size) {
    const int*   ids  = (const int*)  d_in[0];
    const float* pos  = (const float*)d_in[1];
    const float* symt = (const float*)d_in[2];
    const float* layt = (const float*)d_in[3];
    const float* relW = (const float*)d_in[4];
    const float* relb = (const float*)d_in[5];
    const float* h1W  = (const float*)d_in[6];
    const float* h1b  = (const float*)d_in[7];
    const float* h2W  = (const float*)d_in[8];
    const float* h2b  = (const float*)d_in[9];
    const float* outW = (const float*)d_in[10];
    const float* outb = (const float*)d_in[11];
    float* out = (float*)d_out;

    float *pA, *pW, *pWc, *pH, *pS0;
    cudaGetSymbolAddress((void**)&pA,  g_A);
    cudaGetSymbolAddress((void**)&pW,  g_Wfull);
    cudaGetSymbolAddress((void**)&pWc, g_Wcat);
    cudaGetSymbolAddress((void**)&pH,  g_H);
    cudaGetSymbolAddress((void**)&pS0, g_S0);

    cudaFuncSetAttribute((const void*)mgemm2<0,32>,
                         cudaFuncAttributeMaxDynamicSharedMemorySize, SMB(32));
    cudaFuncSetAttribute((const void*)mgemm2<1,64>,
                         cudaFuncAttributeMaxDynamicSharedMemorySize, SMB(64));

    // order: slot #3 (0-indexed) = k_mgband -> profiled by ncu
    k_pre   <<<4096 + 128, 256>>>(ids, symt, layt, pos);
    k_sort  <<<B_, N_>>>(pos);
    k_prefix<<<B_ * 8, 1024>>>();
    k_mgband<<<dim3(8, 8, 8), 256>>>();
    {
        int total = KA_ * D_ + 1024 * D_ + 1024;
        k_weights<<<(total + 255) / 256, 256>>>(relW, relb, h1W, h1b, outW, outb);
    }

    float* d_sym = out + OFF_SYM;
    // grammar: symbols = S0 + A @ Wfull  (BN=32 -> 256 blocks)
    mgemm2<0,32><<<dim3(D_ / 32, BN_ / 128), 256, SMB(32)>>>(
        pA, KA_, pW, D_, KA_, pS0, d_sym, nullptr);
    // fused heads (gelu -> g_H) + output projection (-> out)
    mgemm2<1,64><<<dim3(1024 / 64, BN_ / 128), 256, SMB(64)>>>(
        d_sym, D_, pWc, 1024, D_, nullptr, pH, out);

    k_interp<<<BN_, 96>>>(h2W, h2b, out);
}